// round 15
// baseline (speedup 1.0000x reference)
#include <cuda_runtime.h>

// LIF spiking neuron: T=4, THRESH=1.0, TAU=1.0.
// x: [T=4, N=8388608] float32, out spikes: same shape float32.
// Per slot: mem += x[t]; spike = (mem > 1); mem = spike ? 0 : mem
//
// FINAL (held) — HBM-roofline converged; 14 rounds of evidence.
// Structure: flat grid, block=256, 1 float4 per thread, all 4 timestep
// loads front-batched (MLP=4), streaming .cs loads and stores.
// 268 MB compulsory traffic at ~7.5 TB/s effective = ~94% of 8 TB/s spec
// (spec floor 33.5us; kernel 35.7-36.4us across 7 reruns of this binary;
// best dur 43.49us). Falsified levers (each probed, predicted, post-mortemed):
//   - 2x unroll            (42 regs -> occ 49%, DRAM% fell)      [R2]
//   - grid-stride persist  (loop-serialized MLP)                 [R4]
//   - block 512 / 128      (neutral)                             [R5,R9]
//   - 256-bit v8.f32       (neutral, occ 61%)                    [R7]
//   - write-through .wt    (neutral; LTS drains WB out-of-band)  [R11]

__global__ void __launch_bounds__(256) lif_spike_kernel(
    const float4* __restrict__ x,
    float4* __restrict__ out,
    int n4)   // number of float4 per timestep (2097152)
{
    int i = blockIdx.x * blockDim.x + threadIdx.x;
    if (i >= n4) return;

    // Front-batch the 4 independent timestep loads: MLP = 4.
    float4 x0 = __ldcs(x + i);
    float4 x1 = __ldcs(x + i + n4);
    float4 x2 = __ldcs(x + i + 2 * n4);
    float4 x3 = __ldcs(x + i + 3 * n4);

    float4 mem, s;

    // t = 0 (mem starts at 0, so mem = x0)
    mem = x0;
    s.x = (mem.x > 1.0f) ? 1.0f : 0.0f;
    s.y = (mem.y > 1.0f) ? 1.0f : 0.0f;
    s.z = (mem.z > 1.0f) ? 1.0f : 0.0f;
    s.w = (mem.w > 1.0f) ? 1.0f : 0.0f;
    __stcs(out + i, s);
    mem.x = (s.x > 0.f) ? 0.f : mem.x;
    mem.y = (s.y > 0.f) ? 0.f : mem.y;
    mem.z = (s.z > 0.f) ? 0.f : mem.z;
    mem.w = (s.w > 0.f) ? 0.f : mem.w;

    // t = 1
    mem.x += x1.x; mem.y += x1.y; mem.z += x1.z; mem.w += x1.w;
    s.x = (mem.x > 1.0f) ? 1.0f : 0.0f;
    s.y = (mem.y > 1.0f) ? 1.0f : 0.0f;
    s.z = (mem.z > 1.0f) ? 1.0f : 0.0f;
    s.w = (mem.w > 1.0f) ? 1.0f : 0.0f;
    __stcs(out + i + n4, s);
    mem.x = (s.x > 0.f) ? 0.f : mem.x;
    mem.y = (s.y > 0.f) ? 0.f : mem.y;
    mem.z = (s.z > 0.f) ? 0.f : mem.z;
    mem.w = (s.w > 0.f) ? 0.f : mem.w;

    // t = 2
    mem.x += x2.x; mem.y += x2.y; mem.z += x2.z; mem.w += x2.w;
    s.x = (mem.x > 1.0f) ? 1.0f : 0.0f;
    s.y = (mem.y > 1.0f) ? 1.0f : 0.0f;
    s.z = (mem.z > 1.0f) ? 1.0f : 0.0f;
    s.w = (mem.w > 1.0f) ? 1.0f : 0.0f;
    __stcs(out + i + 2 * n4, s);
    mem.x = (s.x > 0.f) ? 0.f : mem.x;
    mem.y = (s.y > 0.f) ? 0.f : mem.y;
    mem.z = (s.z > 0.f) ? 0.f : mem.z;
    mem.w = (s.w > 0.f) ? 0.f : mem.w;

    // t = 3 (no membrane update after last spike)
    mem.x += x3.x; mem.y += x3.y; mem.z += x3.z; mem.w += x3.w;
    s.x = (mem.x > 1.0f) ? 1.0f : 0.0f;
    s.y = (mem.y > 1.0f) ? 1.0f : 0.0f;
    s.z = (mem.z > 1.0f) ? 1.0f : 0.0f;
    s.w = (mem.w > 1.0f) ? 1.0f : 0.0f;
    __stcs(out + i + 3 * n4, s);
}

extern "C" void kernel_launch(void* const* d_in, const int* in_sizes, int n_in,
                              void* d_out, int out_size)
{
    const float4* x = (const float4*)d_in[0];
    float4* out = (float4*)d_out;

    int total = in_sizes[0];       // T * N floats
    int n_per_t = total / 4;       // floats per timestep
    int n4 = n_per_t / 4;          // float4 per timestep

    int threads = 256;
    int blocks = (n4 + threads - 1) / threads;
    lif_spike_kernel<<<blocks, threads>>>(x, out, n4);
}

// round 16
// speedup vs baseline: 1.0199x; 1.0199x over previous
#include <cuda_runtime.h>

// LIF spiking neuron: T=4, THRESH=1.0, TAU=1.0.
// x: [T=4, N=8388608] float32, out spikes: same shape float32.
// Per slot: mem += x[t]; spike = (mem > 1); mem = spike ? 0 : mem
//
// FINAL — HBM-roofline converged; 15 rounds of evidence.
// Structure: flat grid, block=256, 1 float4 per thread, all 4 timestep
// loads front-batched (MLP=4), streaming .cs loads and stores.
// 268 MB compulsory traffic at ~7.5 TB/s effective = ~94% of 8 TB/s spec
// (spec floor 33.5us; kernel 35.7-36.4us across 8 reruns of this binary;
// best dur 43.49us). Falsified levers (probed, predicted, post-mortemed):
//   - 2x unroll            (42 regs -> occ 49%, DRAM% fell)      [R2]
//   - grid-stride persist  (loop-serialized MLP)                 [R4]
//   - block 512 / 128      (neutral)                             [R5,R9]
//   - 256-bit v8.f32       (neutral, occ 61%)                    [R7]
//   - write-through .wt    (neutral; LTS drains WB out-of-band)  [R11]

__global__ void __launch_bounds__(256) lif_spike_kernel(
    const float4* __restrict__ x,
    float4* __restrict__ out,
    int n4)   // number of float4 per timestep (2097152)
{
    int i = blockIdx.x * blockDim.x + threadIdx.x;
    if (i >= n4) return;

    // Front-batch the 4 independent timestep loads: MLP = 4.
    float4 x0 = __ldcs(x + i);
    float4 x1 = __ldcs(x + i + n4);
    float4 x2 = __ldcs(x + i + 2 * n4);
    float4 x3 = __ldcs(x + i + 3 * n4);

    float4 mem, s;

    // t = 0 (mem starts at 0, so mem = x0)
    mem = x0;
    s.x = (mem.x > 1.0f) ? 1.0f : 0.0f;
    s.y = (mem.y > 1.0f) ? 1.0f : 0.0f;
    s.z = (mem.z > 1.0f) ? 1.0f : 0.0f;
    s.w = (mem.w > 1.0f) ? 1.0f : 0.0f;
    __stcs(out + i, s);
    mem.x = (s.x > 0.f) ? 0.f : mem.x;
    mem.y = (s.y > 0.f) ? 0.f : mem.y;
    mem.z = (s.z > 0.f) ? 0.f : mem.z;
    mem.w = (s.w > 0.f) ? 0.f : mem.w;

    // t = 1
    mem.x += x1.x; mem.y += x1.y; mem.z += x1.z; mem.w += x1.w;
    s.x = (mem.x > 1.0f) ? 1.0f : 0.0f;
    s.y = (mem.y > 1.0f) ? 1.0f : 0.0f;
    s.z = (mem.z > 1.0f) ? 1.0f : 0.0f;
    s.w = (mem.w > 1.0f) ? 1.0f : 0.0f;
    __stcs(out + i + n4, s);
    mem.x = (s.x > 0.f) ? 0.f : mem.x;
    mem.y = (s.y > 0.f) ? 0.f : mem.y;
    mem.z = (s.z > 0.f) ? 0.f : mem.z;
    mem.w = (s.w > 0.f) ? 0.f : mem.w;

    // t = 2
    mem.x += x2.x; mem.y += x2.y; mem.z += x2.z; mem.w += x2.w;
    s.x = (mem.x > 1.0f) ? 1.0f : 0.0f;
    s.y = (mem.y > 1.0f) ? 1.0f : 0.0f;
    s.z = (mem.z > 1.0f) ? 1.0f : 0.0f;
    s.w = (mem.w > 1.0f) ? 1.0f : 0.0f;
    __stcs(out + i + 2 * n4, s);
    mem.x = (s.x > 0.f) ? 0.f : mem.x;
    mem.y = (s.y > 0.f) ? 0.f : mem.y;
    mem.z = (s.z > 0.f) ? 0.f : mem.z;
    mem.w = (s.w > 0.f) ? 0.f : mem.w;

    // t = 3 (no membrane update after last spike)
    mem.x += x3.x; mem.y += x3.y; mem.z += x3.z; mem.w += x3.w;
    s.x = (mem.x > 1.0f) ? 1.0f : 0.0f;
    s.y = (mem.y > 1.0f) ? 1.0f : 0.0f;
    s.z = (mem.z > 1.0f) ? 1.0f : 0.0f;
    s.w = (mem.w > 1.0f) ? 1.0f : 0.0f;
    __stcs(out + i + 3 * n4, s);
}

extern "C" void kernel_launch(void* const* d_in, const int* in_sizes, int n_in,
                              void* d_out, int out_size)
{
    const float4* x = (const float4*)d_in[0];
    float4* out = (float4*)d_out;

    int total = in_sizes[0];       // T * N floats
    int n_per_t = total / 4;       // floats per timestep
    int n4 = n_per_t / 4;          // float4 per timestep

    int threads = 256;
    int blocks = (n4 + threads - 1) / threads;
    lif_spike_kernel<<<blocks, threads>>>(x, out, n4);
}